// round 1
// baseline (speedup 1.0000x reference)
#include <cuda_runtime.h>
#include <cuda_bf16.h>
#include <math.h>

#define S_  2048
#define E_  2048
#define H_  16
#define QR_ 512
#define KVR_ 512
#define DR_ 64
#define DV_ 128
#define DQK_ 192   // DV + DR

// ---------------- scratch (device globals: no allocation allowed) ----------
__device__ float g_cq [S_ * QR_];
__device__ float g_ckv[S_ * KVR_];
__device__ float g_qc [S_ * (H_*DV_)];
__device__ float g_qr [S_ * (H_*DR_)];
__device__ float g_kv [S_ * (H_*2*DV_)];
__device__ float g_kr [S_ * DR_];
__device__ __nv_bfloat16 g_q[(size_t)S_ * H_ * DQK_];
__device__ __nv_bfloat16 g_k[(size_t)S_ * H_ * DQK_];
__device__ __nv_bfloat16 g_v[(size_t)S_ * H_ * DV_];
__device__ __nv_bfloat16 g_logits[(size_t)H_ * S_ * S_];
__device__ __nv_bfloat16 g_probs [(size_t)H_ * S_ * S_];
__device__ float g_attn[S_ * (H_*DV_)];

// ---------------- helpers ----------------
__device__ __forceinline__ float to_f(float x) { return x; }
__device__ __forceinline__ float to_f(__nv_bfloat16 x) { return __bfloat162float(x); }

__device__ __forceinline__ void st_c(float* p, float v) { *p = v; }
__device__ __forceinline__ void st_c(__nv_bfloat16* p, float v) { *p = __float2bfloat16(v); }

// ---------------- generic strided/batched GEMM ----------------
// C[m,n] = sum_k A(m,k) * B(n,k)
// A(m,k) = A[m*Asm + k*Ask], B(n,k) = B[n*Bsn + k*Bsk], C(m,n) = C[m*Csm + n]
// batch z adds Abat/Bbat/Cbat offsets. fp32 accumulate.
// RB: round result to bf16 before storing (even when TC=float).
#define BM 64
#define BN 64
#define BK 16

template <typename TA, typename TB, typename TC, bool RB>
__global__ void gemm_k(const TA* __restrict__ A, const TB* __restrict__ B, TC* __restrict__ C,
                       int M, int N, int K,
                       long Asm_, long Ask, long Bsn, long Bsk, long Csm,
                       long Abat, long Bbat, long Cbat)
{
    __shared__ float sA[BK][BM + 1];
    __shared__ float sB[BK][BN + 1];

    A += (long)blockIdx.z * Abat;
    B += (long)blockIdx.z * Bbat;
    C += (long)blockIdx.z * Cbat;

    const int m0 = blockIdx.y * BM;
    const int n0 = blockIdx.x * BN;
    const int tid = threadIdx.x;          // 256 threads
    const int tx = tid & 15;
    const int ty = tid >> 4;

    float acc[4][4];
#pragma unroll
    for (int i = 0; i < 4; i++)
#pragma unroll
        for (int j = 0; j < 4; j++) acc[i][j] = 0.f;

    for (int kk = 0; kk < K; kk += BK) {
        // ---- load A tile ----
        if (Ask == 1) {
#pragma unroll
            for (int l = 0; l < 4; l++) {
                int idx = tid + l * 256;
                int k = idx & 15, i = idx >> 4;
                int m = m0 + i, kg = kk + k;
                sA[k][i] = (m < M && kg < K) ? to_f(A[(long)m * Asm_ + kg]) : 0.f;
            }
        } else {
#pragma unroll
            for (int l = 0; l < 4; l++) {
                int idx = tid + l * 256;
                int i = idx & 63, k = idx >> 6;
                int m = m0 + i, kg = kk + k;
                sA[k][i] = (m < M && kg < K) ? to_f(A[(long)m * Asm_ + (long)kg * Ask]) : 0.f;
            }
        }
        // ---- load B tile ----
        if (Bsk == 1) {
#pragma unroll
            for (int l = 0; l < 4; l++) {
                int idx = tid + l * 256;
                int k = idx & 15, i = idx >> 4;
                int n = n0 + i, kg = kk + k;
                sB[k][i] = (n < N && kg < K) ? to_f(B[(long)n * Bsn + kg]) : 0.f;
            }
        } else {
#pragma unroll
            for (int l = 0; l < 4; l++) {
                int idx = tid + l * 256;
                int i = idx & 63, k = idx >> 6;
                int n = n0 + i, kg = kk + k;
                sB[k][i] = (n < N && kg < K) ? to_f(B[(long)n * Bsn + (long)kg * Bsk]) : 0.f;
            }
        }
        __syncthreads();

#pragma unroll
        for (int k = 0; k < BK; k++) {
            float ra[4], rb[4];
#pragma unroll
            for (int i = 0; i < 4; i++) ra[i] = sA[k][ty * 4 + i];
#pragma unroll
            for (int j = 0; j < 4; j++) rb[j] = sB[k][tx * 4 + j];
#pragma unroll
            for (int i = 0; i < 4; i++)
#pragma unroll
                for (int j = 0; j < 4; j++) acc[i][j] += ra[i] * rb[j];
        }
        __syncthreads();
    }

#pragma unroll
    for (int i = 0; i < 4; i++) {
        int m = m0 + ty * 4 + i;
        if (m >= M) continue;
#pragma unroll
        for (int j = 0; j < 4; j++) {
            int n = n0 + tx * 4 + j;
            if (n >= N) continue;
            float v = acc[i][j];
            if (RB) v = __bfloat162float(__float2bfloat16(v));
            st_c(&C[(long)m * Csm + n], v);
        }
    }
}

// ---------------- pack q/k/v (bf16) + RoPE ----------------
__global__ void pack_k(const float* __restrict__ qc, const float* __restrict__ qr,
                       const float* __restrict__ kv, const float* __restrict__ kr,
                       __nv_bfloat16* __restrict__ q, __nv_bfloat16* __restrict__ k,
                       __nv_bfloat16* __restrict__ v)
{
    const int s = blockIdx.x;
    const int tid = threadIdx.x;  // 256

    __shared__ float ssin[32], scos[32];
    if (tid < 32) {
        // match jnp fp32 semantics: inv_freq rounded to fp32, angle = fp32(s * inv_freq),
        // trig of that angle evaluated in double (== true sin of the fp32 argument)
        double invf_d = pow(10000.0, -((double)(2 * tid)) / 64.0);
        float invf = (float)invf_d;
        float ang = (float)s * invf;
        double a = (double)ang;
        ssin[tid] = (float)sin(a);
        scos[tid] = (float)cos(a);
    }
    __syncthreads();

    // content parts + v
    for (int idx = tid; idx < H_ * DV_; idx += 256) {
        int h = idx >> 7, d = idx & 127;
        q[((long)s * H_ + h) * DQK_ + d] = __float2bfloat16(qc[(long)s * (H_*DV_) + idx]);
        k[((long)s * H_ + h) * DQK_ + d] = __float2bfloat16(kv[(long)s * (H_*2*DV_) + idx]);
        v[((long)s * H_ + h) * DV_ + d]  = __float2bfloat16(kv[(long)s * (H_*2*DV_) + H_*DV_ + idx]);
    }

    // q rope: 16 heads x 32 pairs
    for (int idx = tid; idx < H_ * 32; idx += 256) {
        int h = idx >> 5, j = idx & 31;
        float x1 = qr[(long)s * (H_*DR_) + h * DR_ + j];
        float x2 = qr[(long)s * (H_*DR_) + h * DR_ + 32 + j];
        float sn = ssin[j], cs = scos[j];
        q[((long)s * H_ + h) * DQK_ + DV_ + j]      = __float2bfloat16(x1 * cs - x2 * sn);
        q[((long)s * H_ + h) * DQK_ + DV_ + 32 + j] = __float2bfloat16(x2 * cs + x1 * sn);
    }

    // k rope (shared across heads)
    if (tid < 32) {
        int j = tid;
        float x1 = kr[(long)s * DR_ + j];
        float x2 = kr[(long)s * DR_ + 32 + j];
        float sn = ssin[j], cs = scos[j];
        float r1 = x1 * cs - x2 * sn;
        float r2 = x2 * cs + x1 * sn;
#pragma unroll
        for (int h = 0; h < H_; h++) {
            k[((long)s * H_ + h) * DQK_ + DV_ + j]      = __float2bfloat16(r1);
            k[((long)s * H_ + h) * DQK_ + DV_ + 32 + j] = __float2bfloat16(r2);
        }
    }
}

// ---------------- softmax over bf16 logits -> bf16 probs ----------------
__global__ void softmax_k(const __nv_bfloat16* __restrict__ L,
                          __nv_bfloat16* __restrict__ P, float scale)
{
    const int s = blockIdx.x;
    const int h = blockIdx.y;
    const __nv_bfloat16* row = L + ((long)h * S_ + s) * S_;
    __nv_bfloat16* prow = P + ((long)h * S_ + s) * S_;
    const int tid = threadIdx.x;  // 256, 8 elems each

    float v[8];
    float mx = -1e30f;
#pragma unroll
    for (int i = 0; i < 8; i++) {
        v[i] = __bfloat162float(row[tid + i * 256]) * scale;
        mx = fmaxf(mx, v[i]);
    }
    __shared__ float red[256];
    red[tid] = mx;
    __syncthreads();
    for (int st = 128; st > 0; st >>= 1) {
        if (tid < st) red[tid] = fmaxf(red[tid], red[tid + st]);
        __syncthreads();
    }
    mx = red[0];
    __syncthreads();

    float sum = 0.f;
#pragma unroll
    for (int i = 0; i < 8; i++) {
        v[i] = expf(v[i] - mx);
        sum += v[i];
    }
    red[tid] = sum;
    __syncthreads();
    for (int st = 128; st > 0; st >>= 1) {
        if (tid < st) red[tid] += red[tid + st];
        __syncthreads();
    }
    float tot = red[0];
#pragma unroll
    for (int i = 0; i < 8; i++)
        prow[tid + i * 256] = __float2bfloat16(v[i] / tot);
}

// ---------------- orchestration ----------------
extern "C" void kernel_launch(void* const* d_in, const int* in_sizes, int n_in,
                              void* d_out, int out_size)
{
    (void)in_sizes; (void)n_in; (void)out_size;
    const float* x       = (const float*)d_in[0];
    const float* wq_down = (const float*)d_in[1];
    const float* wq_up   = (const float*)d_in[2];
    const float* wq_rope = (const float*)d_in[3];
    const float* wkv_down= (const float*)d_in[4];
    const float* wkv_up  = (const float*)d_in[5];
    const float* wk_rope = (const float*)d_in[6];
    const float* wo      = (const float*)d_in[7];
    float* out = (float*)d_out;

    float *cq, *ckv, *qc, *qr, *kv, *kr, *attn;
    __nv_bfloat16 *q, *k, *v, *logits, *probs;
    cudaGetSymbolAddress((void**)&cq,   g_cq);
    cudaGetSymbolAddress((void**)&ckv,  g_ckv);
    cudaGetSymbolAddress((void**)&qc,   g_qc);
    cudaGetSymbolAddress((void**)&qr,   g_qr);
    cudaGetSymbolAddress((void**)&kv,   g_kv);
    cudaGetSymbolAddress((void**)&kr,   g_kr);
    cudaGetSymbolAddress((void**)&attn, g_attn);
    cudaGetSymbolAddress((void**)&q,      g_q);
    cudaGetSymbolAddress((void**)&k,      g_k);
    cudaGetSymbolAddress((void**)&v,      g_v);
    cudaGetSymbolAddress((void**)&logits, g_logits);
    cudaGetSymbolAddress((void**)&probs,  g_probs);

    dim3 blk(256);
    auto grid = [](int M, int N, int batch) {
        return dim3((N + BN - 1) / BN, (M + BM - 1) / BM, batch);
    };

    // c_q = x @ wq_down^T        [2048,512] K=2048
    gemm_k<float, float, float, false><<<grid(S_, QR_, 1), blk>>>(
        x, wq_down, cq, S_, QR_, E_, E_, 1, E_, 1, QR_, 0, 0, 0);
    // c_kv = x @ wkv_down^T      [2048,512] K=2048
    gemm_k<float, float, float, false><<<grid(S_, KVR_, 1), blk>>>(
        x, wkv_down, ckv, S_, KVR_, E_, E_, 1, E_, 1, KVR_, 0, 0, 0);
    // qc = c_q @ wq_up^T         [2048,2048] K=512
    gemm_k<float, float, float, false><<<grid(S_, H_*DV_, 1), blk>>>(
        cq, wq_up, qc, S_, H_*DV_, QR_, QR_, 1, QR_, 1, H_*DV_, 0, 0, 0);
    // qr = c_q @ wq_rope^T       [2048,1024] K=512
    gemm_k<float, float, float, false><<<grid(S_, H_*DR_, 1), blk>>>(
        cq, wq_rope, qr, S_, H_*DR_, QR_, QR_, 1, QR_, 1, H_*DR_, 0, 0, 0);
    // kv = c_kv @ wkv_up^T       [2048,4096] K=512
    gemm_k<float, float, float, false><<<grid(S_, H_*2*DV_, 1), blk>>>(
        ckv, wkv_up, kv, S_, H_*2*DV_, KVR_, KVR_, 1, KVR_, 1, H_*2*DV_, 0, 0, 0);
    // kr = x @ wk_rope^T         [2048,64] K=2048
    gemm_k<float, float, float, false><<<grid(S_, DR_, 1), blk>>>(
        x, wk_rope, kr, S_, DR_, E_, E_, 1, E_, 1, DR_, 0, 0, 0);

    // pack + rope -> bf16 q/k/v
    pack_k<<<S_, 256>>>(qc, qr, kv, kr, q, k, v);

    // logits[h,s,t] = bf16( sum_d q[s,h,d] * k[t,h,d] )   (batched over h)
    gemm_k<__nv_bfloat16, __nv_bfloat16, __nv_bfloat16, false><<<grid(S_, S_, H_), blk>>>(
        q, k, logits, S_, S_, DQK_,
        (long)H_*DQK_, 1, (long)H_*DQK_, 1, S_,
        DQK_, DQK_, (long)S_*S_);

    // softmax (scale applied here, matching ref's astype(f32)*scale)
    {
        dim3 g(S_, H_);
        softmax_k<<<g, 256>>>(logits, probs, 1.0f / sqrtf((float)(DV_ + DR_)));
    }

    // attn[s,h,d] = bf16( sum_t probs[h,s,t] * v[t,h,d] )  stored as fp32
    gemm_k<__nv_bfloat16, __nv_bfloat16, float, true><<<grid(S_, DV_, H_), blk>>>(
        probs, v, attn, S_, DV_, S_,
        S_, 1, 1, (long)H_*DV_, (long)H_*DV_,
        (long)S_*S_, DV_, DV_);

    // out = attn_flat @ wo^T     [2048,2048] K=2048 (fp32)
    gemm_k<float, float, float, false><<<grid(S_, E_, 1), blk>>>(
        attn, wo, out, S_, E_, H_*DV_, H_*DV_, 1, H_*DV_, 1, E_, 0, 0, 0);
}

// round 4
// speedup vs baseline: 2.3203x; 2.3203x over previous
#include <cuda_runtime.h>
#include <cuda_bf16.h>
#include <math.h>
#include <stdint.h>

#define S_  2048
#define E_  2048
#define H_  16
#define QR_ 512
#define KVR_ 512
#define DR_ 64
#define DV_ 128
#define DQK_ 192   // DV + DR

typedef __nv_bfloat16 bf16;

// ---------------- scratch (device globals) ----------------
__device__ float g_cq [S_ * QR_];
__device__ float g_ckv[S_ * KVR_];
__device__ float g_qc [S_ * (H_*DV_)];
__device__ float g_qr [S_ * (H_*DR_)];
__device__ float g_kv [S_ * (H_*2*DV_)];
__device__ float g_kr [S_ * DR_];
__device__ float g_attn[S_ * (H_*DV_)];          // fp32 holding exactly-bf16 values
__device__ bf16 g_q[(size_t)H_ * S_ * DQK_];
__device__ bf16 g_k[(size_t)H_ * S_ * DQK_];
__device__ bf16 g_v[(size_t)H_ * S_ * DV_];
__device__ bf16 g_vT[(size_t)H_ * DV_ * S_];
__device__ bf16 g_logits[(size_t)H_ * S_ * S_];
__device__ bf16 g_probs [(size_t)H_ * S_ * S_];

// ---------------- tf32 helpers ----------------
__device__ __forceinline__ uint32_t f2tf32(float x) {
    uint32_t r;
    asm("cvt.rna.tf32.f32 %0, %1;" : "=r"(r) : "f"(x));
    return r;
}

#define MMA_TF32(c, a, b) \
    asm volatile( \
        "mma.sync.aligned.m16n8k8.row.col.f32.tf32.tf32.f32 " \
        "{%0,%1,%2,%3}, {%4,%5,%6,%7}, {%8,%9}, {%0,%1,%2,%3};" \
        : "+f"((c)[0]), "+f"((c)[1]), "+f"((c)[2]), "+f"((c)[3]) \
        : "r"((a)[0]), "r"((a)[1]), "r"((a)[2]), "r"((a)[3]), \
          "r"((b)[0]), "r"((b)[1]))

#define MMA_BF16(c, a, b) \
    asm volatile( \
        "mma.sync.aligned.m16n8k16.row.col.f32.bf16.bf16.f32 " \
        "{%0,%1,%2,%3}, {%4,%5,%6,%7}, {%8,%9}, {%0,%1,%2,%3};" \
        : "+f"((c)[0]), "+f"((c)[1]), "+f"((c)[2]), "+f"((c)[3]) \
        : "r"((a)[0]), "r"((a)[1]), "r"((a)[2]), "r"((a)[3]), \
          "r"((b)[0]), "r"((b)[1]))

// ============================================================================
// 3xTF32 GEMM, chunked-IEEE accumulation:
// each FBK=16 tile's mma chain starts from a ZERO fragment; fragment is added
// to the fp32 accumulator with IEEE FADD (RN). Kills HMMA truncation bias.
// ============================================================================
#define FBM 128
#define FBN 128
#define FBK 16
#define FPAD 20

template <bool A_EXACT>
__global__ __launch_bounds__(256)
void tf32_gemm(const float* __restrict__ A, const float* __restrict__ B,
               float* __restrict__ C, int M, int N, int K,
               long lda, long ldb, long ldc)
{
    __shared__ float sA[FBM * FPAD];
    __shared__ float sB[FBN * FPAD];

    const int m0 = blockIdx.y * FBM;
    const int n0 = blockIdx.x * FBN;
    const int tid = threadIdx.x;
    const int warp = tid >> 5;
    const int lane = tid & 31;
    const int gid = lane >> 2;
    const int tig = lane & 3;
    const int wm = (warp >> 1) * 32;
    const int wn = (warp & 1) * 64;

    float acc[2][8][4];
#pragma unroll
    for (int mt = 0; mt < 2; mt++)
#pragma unroll
        for (int nt = 0; nt < 8; nt++)
#pragma unroll
            for (int r = 0; r < 4; r++) acc[mt][nt][r] = 0.f;

    for (int kk = 0; kk < K; kk += FBK) {
#pragma unroll
        for (int it = 0; it < 2; it++) {
            int idx = tid + it * 256;
            int row = idx >> 2, ch = idx & 3;
            float4 va = *(const float4*)(A + (long)(m0 + row) * lda + kk + ch * 4);
            *(float4*)&sA[row * FPAD + ch * 4] = va;
            float4 vb;
            if (n0 + row < N)
                vb = *(const float4*)(B + (long)(n0 + row) * ldb + kk + ch * 4);
            else
                vb = make_float4(0.f, 0.f, 0.f, 0.f);
            *(float4*)&sB[row * FPAD + ch * 4] = vb;
        }
        __syncthreads();

        // A fragments for both ks sub-tiles
        uint32_t ah[2][2][4], al[2][2][4];
#pragma unroll
        for (int ks = 0; ks < 2; ks++)
#pragma unroll
            for (int mt = 0; mt < 2; mt++)
#pragma unroll
                for (int r = 0; r < 4; r++) {
                    int row = wm + mt * 16 + gid + (r & 1) * 8;
                    int col = ks * 8 + tig + (r >> 1) * 4;
                    float v = sA[row * FPAD + col];
                    uint32_t h = f2tf32(v);
                    ah[ks][mt][r] = h;
                    if (!A_EXACT) al[ks][mt][r] = f2tf32(v - __uint_as_float(h));
                }

#pragma unroll
        for (int nt = 0; nt < 8; nt++) {
            uint32_t bh[2][2], bl[2][2];
#pragma unroll
            for (int ks = 0; ks < 2; ks++)
#pragma unroll
                for (int r = 0; r < 2; r++) {
                    int n = wn + nt * 8 + gid;
                    int kq = ks * 8 + tig + r * 4;
                    float v = sB[n * FPAD + kq];
                    uint32_t h = f2tf32(v);
                    bh[ks][r] = h;
                    bl[ks][r] = f2tf32(v - __uint_as_float(h));
                }
#pragma unroll
            for (int mt = 0; mt < 2; mt++) {
                float f[4] = {0.f, 0.f, 0.f, 0.f};
#pragma unroll
                for (int ks = 0; ks < 2; ks++) {
                    MMA_TF32(f, ah[ks][mt], bh[ks]);
                    MMA_TF32(f, ah[ks][mt], bl[ks]);
                    if (!A_EXACT) MMA_TF32(f, al[ks][mt], bh[ks]);
                }
                float* c = acc[mt][nt];
                c[0] += f[0]; c[1] += f[1]; c[2] += f[2]; c[3] += f[3];
            }
        }
        __syncthreads();
    }

#pragma unroll
    for (int mt = 0; mt < 2; mt++) {
        int row0 = m0 + wm + mt * 16 + gid;
#pragma unroll
        for (int nt = 0; nt < 8; nt++) {
            int n = n0 + wn + nt * 8 + tig * 2;
            if (n >= N) continue;
            float* c = acc[mt][nt];
            C[(long)row0 * ldc + n]         = c[0];
            C[(long)row0 * ldc + n + 1]     = c[1];
            C[(long)(row0+8) * ldc + n]     = c[2];
            C[(long)(row0+8) * ldc + n + 1] = c[3];
        }
    }
}

// ============================================================================
// bf16 tensor-core GEMM, chunked-IEEE accumulation (TBK=32 -> 2 chained mma
// from a zero fragment, then IEEE FADD into fp32 acc).
// ============================================================================
#define TBM 128
#define TBN 128
#define TBK 32
#define PADK 40

template <typename TC, bool RB>
__global__ __launch_bounds__(256)
void bf16_gemm(const bf16* __restrict__ A, const bf16* __restrict__ B,
               TC* __restrict__ C, int M, int N, int K,
               long lda, long ldb, long ldc, long Abat, long Bbat, long Cbat)
{
    __shared__ bf16 sA[TBM * PADK];
    __shared__ bf16 sB[TBN * PADK];

    const long zo = blockIdx.z;
    A += zo * Abat;  B += zo * Bbat;  C += zo * Cbat;

    const int m0 = blockIdx.y * TBM;
    const int n0 = blockIdx.x * TBN;
    const int tid = threadIdx.x;
    const int warp = tid >> 5;
    const int lane = tid & 31;
    const int gid = lane >> 2;
    const int tig = lane & 3;
    const int wm = (warp >> 1) * 32;
    const int wn = (warp & 1) * 64;

    float acc[2][8][4];
#pragma unroll
    for (int mt = 0; mt < 2; mt++)
#pragma unroll
        for (int nt = 0; nt < 8; nt++)
#pragma unroll
            for (int r = 0; r < 4; r++) acc[mt][nt][r] = 0.f;

    for (int kk = 0; kk < K; kk += TBK) {
#pragma unroll
        for (int it = 0; it < 2; it++) {
            int idx = tid + it * 256;
            int row = idx >> 2, ch = idx & 3;
            uint4 va = *(const uint4*)(A + (long)(m0 + row) * lda + kk + ch * 8);
            *(uint4*)&sA[row * PADK + ch * 8] = va;
            uint4 vb;
            if (n0 + row < N)
                vb = *(const uint4*)(B + (long)(n0 + row) * ldb + kk + ch * 8);
            else
                vb = make_uint4(0u, 0u, 0u, 0u);
            *(uint4*)&sB[row * PADK + ch * 8] = vb;
        }
        __syncthreads();

        uint32_t a[2][2][4];   // [ks][mt][reg]
#pragma unroll
        for (int ks = 0; ks < 2; ks++)
#pragma unroll
            for (int mt = 0; mt < 2; mt++)
#pragma unroll
                for (int r = 0; r < 4; r++) {
                    int row = wm + mt * 16 + gid + (r & 1) * 8;
                    int col = ks * 16 + tig * 2 + (r >> 1) * 8;
                    a[ks][mt][r] = *(const uint32_t*)&sA[row * PADK + col];
                }

#pragma unroll
        for (int nt = 0; nt < 8; nt++) {
            uint32_t b[2][2];
#pragma unroll
            for (int ks = 0; ks < 2; ks++)
#pragma unroll
                for (int r = 0; r < 2; r++) {
                    int n  = wn + nt * 8 + gid;
                    int kq = ks * 16 + tig * 2 + r * 8;
                    b[ks][r] = *(const uint32_t*)&sB[n * PADK + kq];
                }
#pragma unroll
            for (int mt = 0; mt < 2; mt++) {
                float f[4] = {0.f, 0.f, 0.f, 0.f};
                MMA_BF16(f, a[0][mt], b[0]);
                MMA_BF16(f, a[1][mt], b[1]);
                float* c = acc[mt][nt];
                c[0] += f[0]; c[1] += f[1]; c[2] += f[2]; c[3] += f[3];
            }
        }
        __syncthreads();
    }

#pragma unroll
    for (int mt = 0; mt < 2; mt++) {
        int row0 = m0 + wm + mt * 16 + gid;
#pragma unroll
        for (int nt = 0; nt < 8; nt++) {
            int n = n0 + wn + nt * 8 + tig * 2;
            if (n >= N) continue;
            float* c = acc[mt][nt];
            if (sizeof(TC) == 4) {
                float* Cf = (float*)C;
                float v0 = c[0], v1 = c[1], v2 = c[2], v3 = c[3];
                if (RB) {
                    v0 = __bfloat162float(__float2bfloat16(v0));
                    v1 = __bfloat162float(__float2bfloat16(v1));
                    v2 = __bfloat162float(__float2bfloat16(v2));
                    v3 = __bfloat162float(__float2bfloat16(v3));
                }
                Cf[(long)row0 * ldc + n]         = v0;
                Cf[(long)row0 * ldc + n + 1]     = v1;
                Cf[(long)(row0+8) * ldc + n]     = v2;
                Cf[(long)(row0+8) * ldc + n + 1] = v3;
            } else {
                bf16* Cb = (bf16*)C;
                *(__nv_bfloat162*)&Cb[(long)row0 * ldc + n] =
                    __nv_bfloat162(__float2bfloat16(c[0]), __float2bfloat16(c[1]));
                *(__nv_bfloat162*)&Cb[(long)(row0+8) * ldc + n] =
                    __nv_bfloat162(__float2bfloat16(c[2]), __float2bfloat16(c[3]));
            }
        }
    }
}

// ---------------- pack q/k/v (bf16, head-major) + RoPE ----------------
__global__ void pack_k(const float* __restrict__ qc, const float* __restrict__ qr,
                       const float* __restrict__ kv, const float* __restrict__ kr,
                       bf16* __restrict__ q, bf16* __restrict__ k, bf16* __restrict__ v)
{
    const int s = blockIdx.x;
    const int tid = threadIdx.x;  // 256

    __shared__ float ssin[32], scos[32];
    if (tid < 32) {
        double invf_d = pow(10000.0, -((double)(2 * tid)) / 64.0);
        float invf = (float)invf_d;
        float ang = (float)s * invf;
        double a = (double)ang;
        ssin[tid] = (float)sin(a);
        scos[tid] = (float)cos(a);
    }
    __syncthreads();

    for (int idx = tid; idx < H_ * DV_; idx += 256) {
        int h = idx >> 7, d = idx & 127;
        q[((long)h * S_ + s) * DQK_ + d] = __float2bfloat16(qc[(long)s * (H_*DV_) + idx]);
        k[((long)h * S_ + s) * DQK_ + d] = __float2bfloat16(kv[(long)s * (H_*2*DV_) + idx]);
        v[((long)h * S_ + s) * DV_ + d]  = __float2bfloat16(kv[(long)s * (H_*2*DV_) + H_*DV_ + idx]);
    }

    for (int idx = tid; idx < H_ * 32; idx += 256) {
        int h = idx >> 5, j = idx & 31;
        float x1 = qr[(long)s * (H_*DR_) + h * DR_ + j];
        float x2 = qr[(long)s * (H_*DR_) + h * DR_ + 32 + j];
        float sn = ssin[j], cs = scos[j];
        q[((long)h * S_ + s) * DQK_ + DV_ + j]      = __float2bfloat16(x1 * cs - x2 * sn);
        q[((long)h * S_ + s) * DQK_ + DV_ + 32 + j] = __float2bfloat16(x2 * cs + x1 * sn);
    }

    if (tid < 32) {
        int j = tid;
        float x1 = kr[(long)s * DR_ + j];
        float x2 = kr[(long)s * DR_ + 32 + j];
        float sn = ssin[j], cs = scos[j];
        float r1 = x1 * cs - x2 * sn;
        float r2 = x2 * cs + x1 * sn;
#pragma unroll
        for (int h = 0; h < H_; h++) {
            k[((long)h * S_ + s) * DQK_ + DV_ + j]      = __float2bfloat16(r1);
            k[((long)h * S_ + s) * DQK_ + DV_ + 32 + j] = __float2bfloat16(r2);
        }
    }
}

// ---------------- transpose v [h][s][d] -> vT [h][d][s] ----------------
__global__ void transpose_v(const bf16* __restrict__ v, bf16* __restrict__ vT)
{
    __shared__ bf16 t[32][33];
    const int h = blockIdx.z;
    const int s0 = blockIdx.x * 32;
    const int d0 = blockIdx.y * 32;
    const int tx = threadIdx.x, ty = threadIdx.y;  // (32, 8)
#pragma unroll
    for (int j = 0; j < 32; j += 8)
        t[ty + j][tx] = v[((long)h * S_ + s0 + ty + j) * DV_ + d0 + tx];
    __syncthreads();
#pragma unroll
    for (int j = 0; j < 32; j += 8)
        vT[((long)h * DV_ + d0 + ty + j) * S_ + s0 + tx] = t[tx][ty + j];
}

// ---------------- softmax over bf16 logits -> bf16 probs ----------------
__global__ void softmax_k(const bf16* __restrict__ L, bf16* __restrict__ P, float scale)
{
    const int s = blockIdx.x;
    const int h = blockIdx.y;
    const bf16* row = L + ((long)h * S_ + s) * S_;
    bf16* prow = P + ((long)h * S_ + s) * S_;
    const int tid = threadIdx.x;  // 256, 8 elems each

    float v[8];
    float mx = -1e30f;
#pragma unroll
    for (int i = 0; i < 8; i++) {
        v[i] = __bfloat162float(row[tid + i * 256]) * scale;
        mx = fmaxf(mx, v[i]);
    }
    __shared__ float red[256];
    red[tid] = mx;
    __syncthreads();
    for (int st = 128; st > 0; st >>= 1) {
        if (tid < st) red[tid] = fmaxf(red[tid], red[tid + st]);
        __syncthreads();
    }
    mx = red[0];
    __syncthreads();

    float sum = 0.f;
#pragma unroll
    for (int i = 0; i < 8; i++) {
        v[i] = expf(v[i] - mx);
        sum += v[i];
    }
    red[tid] = sum;
    __syncthreads();
    for (int st = 128; st > 0; st >>= 1) {
        if (tid < st) red[tid] += red[tid + st];
        __syncthreads();
    }
    float tot = red[0];
#pragma unroll
    for (int i = 0; i < 8; i++)
        prow[tid + i * 256] = __float2bfloat16(v[i] / tot);
}

// ---------------- orchestration ----------------
extern "C" void kernel_launch(void* const* d_in, const int* in_sizes, int n_in,
                              void* d_out, int out_size)
{
    (void)in_sizes; (void)n_in; (void)out_size;
    const float* x       = (const float*)d_in[0];
    const float* wq_down = (const float*)d_in[1];
    const float* wq_up   = (const float*)d_in[2];
    const float* wq_rope = (const float*)d_in[3];
    const float* wkv_down= (const float*)d_in[4];
    const float* wkv_up  = (const float*)d_in[5];
    const float* wk_rope = (const float*)d_in[6];
    const float* wo      = (const float*)d_in[7];
    float* out = (float*)d_out;

    float *cq, *ckv, *qc, *qr, *kvf, *kr, *attn;
    cudaGetSymbolAddress((void**)&cq,  g_cq);
    cudaGetSymbolAddress((void**)&ckv, g_ckv);
    cudaGetSymbolAddress((void**)&qc,  g_qc);
    cudaGetSymbolAddress((void**)&qr,  g_qr);
    cudaGetSymbolAddress((void**)&kvf, g_kv);
    cudaGetSymbolAddress((void**)&kr,  g_kr);
    cudaGetSymbolAddress((void**)&attn, g_attn);

    bf16 *q, *k, *v, *vT, *logits, *probs;
    cudaGetSymbolAddress((void**)&q, g_q);
    cudaGetSymbolAddress((void**)&k, g_k);
    cudaGetSymbolAddress((void**)&v, g_v);
    cudaGetSymbolAddress((void**)&vT, g_vT);
    cudaGetSymbolAddress((void**)&logits, g_logits);
    cudaGetSymbolAddress((void**)&probs, g_probs);

    dim3 blk(256);
    auto fgrid = [](int M, int N) {
        return dim3((N + FBN - 1) / FBN, (M + FBM - 1) / FBM, 1);
    };
    auto bgrid = [](int M, int N, int batch) {
        return dim3((N + TBN - 1) / TBN, (M + TBM - 1) / TBM, batch);
    };

    // 1) down projections (3xTF32, chunked-IEEE ~ fp32)
    tf32_gemm<false><<<fgrid(S_, QR_), blk>>>(x, wq_down, cq, S_, QR_, E_, E_, E_, QR_);
    tf32_gemm<false><<<fgrid(S_, KVR_), blk>>>(x, wkv_down, ckv, S_, KVR_, E_, E_, E_, KVR_);
    tf32_gemm<false><<<fgrid(S_, DR_), blk>>>(x, wk_rope, kr, S_, DR_, E_, E_, E_, DR_);

    // 2) up projections
    tf32_gemm<false><<<fgrid(S_, H_*DV_), blk>>>(cq, wq_up, qc, S_, H_*DV_, QR_, QR_, QR_, H_*DV_);
    tf32_gemm<false><<<fgrid(S_, H_*DR_), blk>>>(cq, wq_rope, qr, S_, H_*DR_, QR_, QR_, QR_, H_*DR_);
    tf32_gemm<false><<<fgrid(S_, H_*2*DV_), blk>>>(ckv, wkv_up, kvf, S_, H_*2*DV_, KVR_, KVR_, KVR_, H_*2*DV_);

    // 3) pack + rope -> head-major bf16 q/k/v ; transpose v
    pack_k<<<S_, 256>>>(qc, qr, kvf, kr, q, k, v);
    {
        dim3 tg(S_/32, DV_/32, H_);
        dim3 tb(32, 8);
        transpose_v<<<tg, tb>>>(v, vT);
    }

    // 4) logits[h] = bf16( q[h] @ k[h]^T )
    bf16_gemm<bf16, false><<<bgrid(S_, S_, H_), blk>>>(
        q, k, logits, S_, S_, DQK_, DQK_, DQK_, S_,
        (long)S_*DQK_, (long)S_*DQK_, (long)S_*S_);

    // 5) softmax (bf16 in, scale, bf16 probs out)
    {
        dim3 g(S_, H_);
        softmax_k<<<g, 256>>>(logits, probs, 1.0f / sqrtf((float)(DV_ + DR_)));
    }

    // 6) attn = bf16-rounded( probs[h] @ v[h] ), stored fp32 interleaved [s][h*DV]
    bf16_gemm<float, true><<<bgrid(S_, DV_, H_), blk>>>(
        probs, vT, attn, S_, DV_, S_, S_, S_, (long)H_*DV_,
        (long)S_*S_, (long)DV_*S_, DV_);

    // 7) out = attn @ wo^T  (attn exactly tf32-representable -> 2 passes)
    tf32_gemm<true><<<fgrid(S_, E_), blk>>>(attn, wo, out, S_, E_, H_*DV_, H_*DV_, H_*DV_, E_);
}

// round 5
// speedup vs baseline: 2.6533x; 1.1435x over previous
#include <cuda_runtime.h>
#include <cuda_bf16.h>
#include <math.h>
#include <stdint.h>

#define S_  2048
#define E_  2048
#define H_  16
#define QR_ 512
#define KVR_ 512
#define DR_ 64
#define DV_ 128
#define DQK_ 192   // DV + DR

typedef __nv_bfloat16 bf16;

// ---------------- scratch (device globals) ----------------
__device__ float g_cq [S_ * QR_];
__device__ float g_ckv[S_ * KVR_];
__device__ float g_qc [S_ * (H_*DV_)];
__device__ float g_qr [S_ * (H_*DR_)];
__device__ float g_kv [S_ * (H_*2*DV_)];
__device__ float g_kr [S_ * DR_];
__device__ float g_attn[S_ * (H_*DV_)];
__device__ bf16 g_q[(size_t)H_ * S_ * DQK_];
__device__ bf16 g_k[(size_t)H_ * S_ * DQK_];
__device__ bf16 g_v[(size_t)H_ * S_ * DV_];
__device__ bf16 g_vT[(size_t)H_ * DV_ * S_];
__device__ bf16 g_logits[(size_t)H_ * S_ * S_];
__device__ bf16 g_probs [(size_t)H_ * S_ * S_];

// ---------------- helpers ----------------
__device__ __forceinline__ uint32_t f2tf32(float x) {
    uint32_t r;
    asm("cvt.rna.tf32.f32 %0, %1;" : "=r"(r) : "f"(x));
    return r;
}

#define MMA_TF32(c, a, b) \
    asm volatile( \
        "mma.sync.aligned.m16n8k8.row.col.f32.tf32.tf32.f32 " \
        "{%0,%1,%2,%3}, {%4,%5,%6,%7}, {%8,%9}, {%0,%1,%2,%3};" \
        : "+f"((c)[0]), "+f"((c)[1]), "+f"((c)[2]), "+f"((c)[3]) \
        : "r"((a)[0]), "r"((a)[1]), "r"((a)[2]), "r"((a)[3]), \
          "r"((b)[0]), "r"((b)[1]))

#define MMA_BF16(c, a, b) \
    asm volatile( \
        "mma.sync.aligned.m16n8k16.row.col.f32.bf16.bf16.f32 " \
        "{%0,%1,%2,%3}, {%4,%5,%6,%7}, {%8,%9}, {%0,%1,%2,%3};" \
        : "+f"((c)[0]), "+f"((c)[1]), "+f"((c)[2]), "+f"((c)[3]) \
        : "r"((a)[0]), "r"((a)[1]), "r"((a)[2]), "r"((a)[3]), \
          "r"((b)[0]), "r"((b)[1]))

#define CP16(dst, src, nbytes) \
    asm volatile("cp.async.cg.shared.global [%0], [%1], 16, %2;" \
                 :: "r"(dst), "l"(src), "r"(nbytes))
#define CP_COMMIT()  asm volatile("cp.async.commit_group;")
#define CP_WAIT0()   asm volatile("cp.async.wait_group 0;")

// ============================================================================
// 3xTF32 GEMM, chunked-IEEE accumulation, cp.async double-buffered.
// ============================================================================
#define FBM 128
#define FBN 128
#define FBK 16
#define FPAD 20

template <bool A_EXACT>
__global__ __launch_bounds__(256)
void tf32_gemm(const float* __restrict__ A, const float* __restrict__ B,
               float* __restrict__ C, int M, int N, int K,
               long lda, long ldb, long ldc)
{
    __shared__ float sA[2][FBM * FPAD];
    __shared__ float sB[2][FBN * FPAD];

    const int m0 = blockIdx.y * FBM;
    const int n0 = blockIdx.x * FBN;
    const int tid = threadIdx.x;
    const int warp = tid >> 5;
    const int lane = tid & 31;
    const int gid = lane >> 2;
    const int tig = lane & 3;
    const int wm = (warp >> 1) * 32;
    const int wn = (warp & 1) * 64;

    // per-thread load descriptors (2 chunks each for A and B)
    const float* aSrc[2];
    const float* bSrc[2];
    uint32_t aOff[2], bOff[2];
    int bPred[2];
    const uint32_t saBase = (uint32_t)__cvta_generic_to_shared(sA);
    const uint32_t sbBase = (uint32_t)__cvta_generic_to_shared(sB);
#pragma unroll
    for (int it = 0; it < 2; it++) {
        int idx = tid + it * 256;
        int row = idx >> 2, ch = idx & 3;
        aSrc[it] = A + (long)(m0 + row) * lda + ch * 4;
        int nrow = n0 + row;
        bPred[it] = (nrow < N) ? 16 : 0;
        if (nrow >= N) nrow = N - 1;
        bSrc[it] = B + (long)nrow * ldb + ch * 4;
        aOff[it] = (uint32_t)(row * FPAD + ch * 4) * 4u;
        bOff[it] = (uint32_t)(row * FPAD + ch * 4) * 4u;
    }
    const uint32_t ABUF = FBM * FPAD * 4u;

    float acc[2][8][4];
#pragma unroll
    for (int mt = 0; mt < 2; mt++)
#pragma unroll
        for (int nt = 0; nt < 8; nt++)
#pragma unroll
            for (int r = 0; r < 4; r++) acc[mt][nt][r] = 0.f;

    const int NT = K / FBK;

    // prologue: tile 0 -> buf 0
#pragma unroll
    for (int it = 0; it < 2; it++) {
        CP16(saBase + aOff[it], aSrc[it], 16);
        CP16(sbBase + bOff[it], bSrc[it], bPred[it]);
    }
    CP_COMMIT();

    for (int t = 0; t < NT; t++) {
        const int cur = t & 1;
        CP_WAIT0();
        __syncthreads();

        if (t + 1 < NT) {
            const long kk = (long)(t + 1) * FBK;
            const uint32_t bo = (cur ^ 1) * ABUF;
#pragma unroll
            for (int it = 0; it < 2; it++) {
                CP16(saBase + bo + aOff[it], aSrc[it] + kk, 16);
                CP16(sbBase + bo + bOff[it], bSrc[it] + kk, bPred[it]);
            }
            CP_COMMIT();
        }

        const float* cA = sA[cur];
        const float* cB = sB[cur];

        uint32_t ah[2][2][4], al[2][2][4];
#pragma unroll
        for (int ks = 0; ks < 2; ks++)
#pragma unroll
            for (int mt = 0; mt < 2; mt++)
#pragma unroll
                for (int r = 0; r < 4; r++) {
                    int row = wm + mt * 16 + gid + (r & 1) * 8;
                    int col = ks * 8 + tig + (r >> 1) * 4;
                    float v = cA[row * FPAD + col];
                    uint32_t h = f2tf32(v);
                    ah[ks][mt][r] = h;
                    if (!A_EXACT) al[ks][mt][r] = f2tf32(v - __uint_as_float(h));
                }

#pragma unroll
        for (int nt = 0; nt < 8; nt++) {
            uint32_t bh[2][2], bl[2][2];
#pragma unroll
            for (int ks = 0; ks < 2; ks++)
#pragma unroll
                for (int r = 0; r < 2; r++) {
                    int n = wn + nt * 8 + gid;
                    int kq = ks * 8 + tig + r * 4;
                    float v = cB[n * FPAD + kq];
                    uint32_t h = f2tf32(v);
                    bh[ks][r] = h;
                    bl[ks][r] = f2tf32(v - __uint_as_float(h));
                }
#pragma unroll
            for (int mt = 0; mt < 2; mt++) {
                float f[4] = {0.f, 0.f, 0.f, 0.f};
#pragma unroll
                for (int ks = 0; ks < 2; ks++) {
                    MMA_TF32(f, ah[ks][mt], bh[ks]);
                    MMA_TF32(f, ah[ks][mt], bl[ks]);
                    if (!A_EXACT) MMA_TF32(f, al[ks][mt], bh[ks]);
                }
                float* c = acc[mt][nt];
                c[0] += f[0]; c[1] += f[1]; c[2] += f[2]; c[3] += f[3];
            }
        }
    }

#pragma unroll
    for (int mt = 0; mt < 2; mt++) {
        int row0 = m0 + wm + mt * 16 + gid;
#pragma unroll
        for (int nt = 0; nt < 8; nt++) {
            int n = n0 + wn + nt * 8 + tig * 2;
            if (n >= N) continue;
            float* c = acc[mt][nt];
            C[(long)row0 * ldc + n]         = c[0];
            C[(long)row0 * ldc + n + 1]     = c[1];
            C[(long)(row0+8) * ldc + n]     = c[2];
            C[(long)(row0+8) * ldc + n + 1] = c[3];
        }
    }
}

// ============================================================================
// bf16 tensor-core GEMM, chunked-IEEE accumulation, cp.async double-buffered.
// ============================================================================
#define TBM 128
#define TBN 128
#define TBK 32
#define PADK 40

template <typename TC, bool RB>
__global__ __launch_bounds__(256)
void bf16_gemm(const bf16* __restrict__ A, const bf16* __restrict__ B,
               TC* __restrict__ C, int M, int N, int K,
               long lda, long ldb, long ldc, long Abat, long Bbat, long Cbat)
{
    __shared__ bf16 sA[2][TBM * PADK];
    __shared__ bf16 sB[2][TBN * PADK];

    const long zo = blockIdx.z;
    A += zo * Abat;  B += zo * Bbat;  C += zo * Cbat;

    const int m0 = blockIdx.y * TBM;
    const int n0 = blockIdx.x * TBN;
    const int tid = threadIdx.x;
    const int warp = tid >> 5;
    const int lane = tid & 31;
    const int gid = lane >> 2;
    const int tig = lane & 3;
    const int wm = (warp >> 1) * 32;
    const int wn = (warp & 1) * 64;

    const bf16* aSrc[2];
    const bf16* bSrc[2];
    uint32_t aOff[2], bOff[2];
    int bPred[2];
    const uint32_t saBase = (uint32_t)__cvta_generic_to_shared(sA);
    const uint32_t sbBase = (uint32_t)__cvta_generic_to_shared(sB);
#pragma unroll
    for (int it = 0; it < 2; it++) {
        int idx = tid + it * 256;
        int row = idx >> 2, ch = idx & 3;
        aSrc[it] = A + (long)(m0 + row) * lda + ch * 8;
        int nrow = n0 + row;
        bPred[it] = (nrow < N) ? 16 : 0;
        if (nrow >= N) nrow = N - 1;
        bSrc[it] = B + (long)nrow * ldb + ch * 8;
        aOff[it] = (uint32_t)(row * PADK + ch * 8) * 2u;
        bOff[it] = (uint32_t)(row * PADK + ch * 8) * 2u;
    }
    const uint32_t ABUF = TBM * PADK * 2u;

    float acc[2][8][4];
#pragma unroll
    for (int mt = 0; mt < 2; mt++)
#pragma unroll
        for (int nt = 0; nt < 8; nt++)
#pragma unroll
            for (int r = 0; r < 4; r++) acc[mt][nt][r] = 0.f;

    const int NT = K / TBK;

#pragma unroll
    for (int it = 0; it < 2; it++) {
        CP16(saBase + aOff[it], aSrc[it], 16);
        CP16(sbBase + bOff[it], bSrc[it], bPred[it]);
    }
    CP_COMMIT();

    for (int t = 0; t < NT; t++) {
        const int cur = t & 1;
        CP_WAIT0();
        __syncthreads();

        if (t + 1 < NT) {
            const long kk = (long)(t + 1) * TBK;
            const uint32_t bo = (cur ^ 1) * ABUF;
#pragma unroll
            for (int it = 0; it < 2; it++) {
                CP16(saBase + bo + aOff[it], aSrc[it] + kk, 16);
                CP16(sbBase + bo + bOff[it], bSrc[it] + kk, bPred[it]);
            }
            CP_COMMIT();
        }

        const bf16* cA = sA[cur];
        const bf16* cB = sB[cur];

        uint32_t a[2][2][4];   // [ks][mt][reg]
#pragma unroll
        for (int ks = 0; ks < 2; ks++)
#pragma unroll
            for (int mt = 0; mt < 2; mt++)
#pragma unroll
                for (int r = 0; r < 4; r++) {
                    int row = wm + mt * 16 + gid + (r & 1) * 8;
                    int col = ks * 16 + tig * 2 + (r >> 1) * 8;
                    a[ks][mt][r] = *(const uint32_t*)&cA[row * PADK + col];
                }

#pragma unroll
        for (int nt = 0; nt < 8; nt++) {
            uint32_t b[2][2];
#pragma unroll
            for (int ks = 0; ks < 2; ks++)
#pragma unroll
                for (int r = 0; r < 2; r++) {
                    int n  = wn + nt * 8 + gid;
                    int kq = ks * 16 + tig * 2 + r * 8;
                    b[ks][r] = *(const uint32_t*)&cB[n * PADK + kq];
                }
#pragma unroll
            for (int mt = 0; mt < 2; mt++) {
                float f[4] = {0.f, 0.f, 0.f, 0.f};
                MMA_BF16(f, a[0][mt], b[0]);
                MMA_BF16(f, a[1][mt], b[1]);
                float* c = acc[mt][nt];
                c[0] += f[0]; c[1] += f[1]; c[2] += f[2]; c[3] += f[3];
            }
        }
    }

#pragma unroll
    for (int mt = 0; mt < 2; mt++) {
        int row0 = m0 + wm + mt * 16 + gid;
#pragma unroll
        for (int nt = 0; nt < 8; nt++) {
            int n = n0 + wn + nt * 8 + tig * 2;
            if (n >= N) continue;
            float* c = acc[mt][nt];
            if (sizeof(TC) == 4) {
                float* Cf = (float*)C;
                float v0 = c[0], v1 = c[1], v2 = c[2], v3 = c[3];
                if (RB) {
                    v0 = __bfloat162float(__float2bfloat16(v0));
                    v1 = __bfloat162float(__float2bfloat16(v1));
                    v2 = __bfloat162float(__float2bfloat16(v2));
                    v3 = __bfloat162float(__float2bfloat16(v3));
                }
                Cf[(long)row0 * ldc + n]         = v0;
                Cf[(long)row0 * ldc + n + 1]     = v1;
                Cf[(long)(row0+8) * ldc + n]     = v2;
                Cf[(long)(row0+8) * ldc + n + 1] = v3;
            } else {
                bf16* Cb = (bf16*)C;
                *(__nv_bfloat162*)&Cb[(long)row0 * ldc + n] =
                    __nv_bfloat162(__float2bfloat16(c[0]), __float2bfloat16(c[1]));
                *(__nv_bfloat162*)&Cb[(long)(row0+8) * ldc + n] =
                    __nv_bfloat162(__float2bfloat16(c[2]), __float2bfloat16(c[3]));
            }
        }
    }
}

// ---------------- pack q/k/v (bf16, head-major) + RoPE ----------------
__global__ void pack_k(const float* __restrict__ qc, const float* __restrict__ qr,
                       const float* __restrict__ kv, const float* __restrict__ kr,
                       bf16* __restrict__ q, bf16* __restrict__ k, bf16* __restrict__ v)
{
    const int s = blockIdx.x;
    const int tid = threadIdx.x;  // 256

    __shared__ float ssin[32], scos[32];
    if (tid < 32) {
        double invf_d = pow(10000.0, -((double)(2 * tid)) / 64.0);
        float invf = (float)invf_d;
        float ang = (float)s * invf;
        double a = (double)ang;
        ssin[tid] = (float)sin(a);
        scos[tid] = (float)cos(a);
    }
    __syncthreads();

    for (int idx = tid; idx < H_ * DV_; idx += 256) {
        int h = idx >> 7, d = idx & 127;
        q[((long)h * S_ + s) * DQK_ + d] = __float2bfloat16(qc[(long)s * (H_*DV_) + idx]);
        k[((long)h * S_ + s) * DQK_ + d] = __float2bfloat16(kv[(long)s * (H_*2*DV_) + idx]);
        v[((long)h * S_ + s) * DV_ + d]  = __float2bfloat16(kv[(long)s * (H_*2*DV_) + H_*DV_ + idx]);
    }

    for (int idx = tid; idx < H_ * 32; idx += 256) {
        int h = idx >> 5, j = idx & 31;
        float x1 = qr[(long)s * (H_*DR_) + h * DR_ + j];
        float x2 = qr[(long)s * (H_*DR_) + h * DR_ + 32 + j];
        float sn = ssin[j], cs = scos[j];
        q[((long)h * S_ + s) * DQK_ + DV_ + j]      = __float2bfloat16(x1 * cs - x2 * sn);
        q[((long)h * S_ + s) * DQK_ + DV_ + 32 + j] = __float2bfloat16(x2 * cs + x1 * sn);
    }

    if (tid < 32) {
        int j = tid;
        float x1 = kr[(long)s * DR_ + j];
        float x2 = kr[(long)s * DR_ + 32 + j];
        float sn = ssin[j], cs = scos[j];
        float r1 = x1 * cs - x2 * sn;
        float r2 = x2 * cs + x1 * sn;
#pragma unroll
        for (int h = 0; h < H_; h++) {
            k[((long)h * S_ + s) * DQK_ + DV_ + j]      = __float2bfloat16(r1);
            k[((long)h * S_ + s) * DQK_ + DV_ + 32 + j] = __float2bfloat16(r2);
        }
    }
}

// ---------------- transpose v [h][s][d] -> vT [h][d][s] ----------------
__global__ void transpose_v(const bf16* __restrict__ v, bf16* __restrict__ vT)
{
    __shared__ bf16 t[32][33];
    const int h = blockIdx.z;
    const int s0 = blockIdx.x * 32;
    const int d0 = blockIdx.y * 32;
    const int tx = threadIdx.x, ty = threadIdx.y;  // (32, 8)
#pragma unroll
    for (int j = 0; j < 32; j += 8)
        t[ty + j][tx] = v[((long)h * S_ + s0 + ty + j) * DV_ + d0 + tx];
    __syncthreads();
#pragma unroll
    for (int j = 0; j < 32; j += 8)
        vT[((long)h * DV_ + d0 + ty + j) * S_ + s0 + tx] = t[tx][ty + j];
}

// ---------------- softmax over bf16 logits -> bf16 probs ----------------
__global__ void softmax_k(const bf16* __restrict__ L, bf16* __restrict__ P, float scale)
{
    const int s = blockIdx.x;
    const int h = blockIdx.y;
    const bf16* row = L + ((long)h * S_ + s) * S_;
    bf16* prow = P + ((long)h * S_ + s) * S_;
    const int tid = threadIdx.x;  // 256, 8 elems each

    float v[8];
    float mx = -1e30f;
#pragma unroll
    for (int i = 0; i < 8; i++) {
        v[i] = __bfloat162float(row[tid + i * 256]) * scale;
        mx = fmaxf(mx, v[i]);
    }
    __shared__ float red[256];
    red[tid] = mx;
    __syncthreads();
    for (int st = 128; st > 0; st >>= 1) {
        if (tid < st) red[tid] = fmaxf(red[tid], red[tid + st]);
        __syncthreads();
    }
    mx = red[0];
    __syncthreads();

    float sum = 0.f;
#pragma unroll
    for (int i = 0; i < 8; i++) {
        v[i] = expf(v[i] - mx);
        sum += v[i];
    }
    red[tid] = sum;
    __syncthreads();
    for (int st = 128; st > 0; st >>= 1) {
        if (tid < st) red[tid] += red[tid + st];
        __syncthreads();
    }
    float tot = red[0];
#pragma unroll
    for (int i = 0; i < 8; i++)
        prow[tid + i * 256] = __float2bfloat16(v[i] / tot);
}

// ---------------- orchestration ----------------
extern "C" void kernel_launch(void* const* d_in, const int* in_sizes, int n_in,
                              void* d_out, int out_size)
{
    (void)in_sizes; (void)n_in; (void)out_size;
    const float* x       = (const float*)d_in[0];
    const float* wq_down = (const float*)d_in[1];
    const float* wq_up   = (const float*)d_in[2];
    const float* wq_rope = (const float*)d_in[3];
    const float* wkv_down= (const float*)d_in[4];
    const float* wkv_up  = (const float*)d_in[5];
    const float* wk_rope = (const float*)d_in[6];
    const float* wo      = (const float*)d_in[7];
    float* out = (float*)d_out;

    float *cq, *ckv, *qc, *qr, *kvf, *kr, *attn;
    cudaGetSymbolAddress((void**)&cq,  g_cq);
    cudaGetSymbolAddress((void**)&ckv, g_ckv);
    cudaGetSymbolAddress((void**)&qc,  g_qc);
    cudaGetSymbolAddress((void**)&qr,  g_qr);
    cudaGetSymbolAddress((void**)&kvf, g_kv);
    cudaGetSymbolAddress((void**)&kr,  g_kr);
    cudaGetSymbolAddress((void**)&attn, g_attn);

    bf16 *q, *k, *v, *vT, *logits, *probs;
    cudaGetSymbolAddress((void**)&q, g_q);
    cudaGetSymbolAddress((void**)&k, g_k);
    cudaGetSymbolAddress((void**)&v, g_v);
    cudaGetSymbolAddress((void**)&vT, g_vT);
    cudaGetSymbolAddress((void**)&logits, g_logits);
    cudaGetSymbolAddress((void**)&probs, g_probs);

    dim3 blk(256);
    auto fgrid = [](int M, int N) {
        return dim3((N + FBN - 1) / FBN, (M + FBM - 1) / FBM, 1);
    };
    auto bgrid = [](int M, int N, int batch) {
        return dim3((N + TBN - 1) / TBN, (M + TBM - 1) / TBM, batch);
    };

    // 1) down projections (3xTF32, chunked-IEEE ~ fp32)
    tf32_gemm<false><<<fgrid(S_, QR_), blk>>>(x, wq_down, cq, S_, QR_, E_, E_, E_, QR_);
    tf32_gemm<false><<<fgrid(S_, KVR_), blk>>>(x, wkv_down, ckv, S_, KVR_, E_, E_, E_, KVR_);
    tf32_gemm<false><<<fgrid(S_, DR_), blk>>>(x, wk_rope, kr, S_, DR_, E_, E_, E_, DR_);

    // 2) up projections
    tf32_gemm<false><<<fgrid(S_, H_*DV_), blk>>>(cq, wq_up, qc, S_, H_*DV_, QR_, QR_, QR_, H_*DV_);
    tf32_gemm<false><<<fgrid(S_, H_*DR_), blk>>>(cq, wq_rope, qr, S_, H_*DR_, QR_, QR_, QR_, H_*DR_);
    tf32_gemm<false><<<fgrid(S_, H_*2*DV_), blk>>>(ckv, wkv_up, kvf, S_, H_*2*DV_, KVR_, KVR_, KVR_, H_*2*DV_);

    // 3) pack + rope -> head-major bf16 q/k/v ; transpose v
    pack_k<<<S_, 256>>>(qc, qr, kvf, kr, q, k, v);
    {
        dim3 tg(S_/32, DV_/32, H_);
        dim3 tb(32, 8);
        transpose_v<<<tg, tb>>>(v, vT);
    }

    // 4) logits[h] = bf16( q[h] @ k[h]^T )
    bf16_gemm<bf16, false><<<bgrid(S_, S_, H_), blk>>>(
        q, k, logits, S_, S_, DQK_, DQK_, DQK_, S_,
        (long)S_*DQK_, (long)S_*DQK_, (long)S_*S_);

    // 5) softmax (bf16 in, scale, bf16 probs out)
    {
        dim3 g(S_, H_);
        softmax_k<<<g, 256>>>(logits, probs, 1.0f / sqrtf((float)(DV_ + DR_)));
    }

    // 6) attn = bf16-rounded( probs[h] @ v[h] ), stored fp32 interleaved [s][h*DV]
    bf16_gemm<float, true><<<bgrid(S_, DV_, H_), blk>>>(
        probs, vT, attn, S_, DV_, S_, S_, S_, (long)H_*DV_,
        (long)S_*S_, (long)DV_*S_, DV_);

    // 7) out = attn @ wo^T  (attn exactly tf32-representable -> 2 passes)
    tf32_gemm<true><<<fgrid(S_, E_), blk>>>(attn, wo, out, S_, E_, H_*DV_, H_*DV_, H_*DV_, E_);
}